// round 17
// baseline (speedup 1.0000x reference)
#include <cuda_runtime.h>
#include <cuda_fp16.h>
#include <cstdint>
#include <cstddef>

#define B_   4
#define S_   2048
#define NH_  16
#define HD_  64
#define HID_ 1024

// ---------------- scratch (device globals; no allocation) -------------------
__device__ __half g_xh[(size_t)B_ * S_ * HID_];          // x in fp16
__device__ __half g_Wqkvt[(size_t)NH_ * 192 * HD_];      // [h][m*64+e][d], Q pre-scaled
__device__ __half g_Qh[(size_t)B_ * NH_ * S_ * HD_];
__device__ __half g_Kh[(size_t)B_ * NH_ * S_ * HD_];
__device__ __half g_Vt[(size_t)B_ * NH_ * S_ * HD_];     // [bh][d][s]
__device__ __half g_ctx[(size_t)B_ * S_ * HID_];
__device__ __half g_Wot[(size_t)HID_ * HID_];            // [n][k]

// ---------------- helpers ----------------------------------------------------
__device__ __forceinline__ unsigned packh(float v0, float v1) {
    unsigned r; asm("cvt.rn.f16x2.f32 %0, %1, %2;" : "=r"(r) : "f"(v1), "f"(v0)); return r;
}
__device__ __forceinline__ unsigned ex2h2(unsigned x) {
    unsigned r; asm("ex2.approx.f16x2 %0, %1;" : "=r"(r) : "r"(x)); return r;
}
__device__ __forceinline__ unsigned hadd2u(unsigned a, unsigned b) {
    unsigned r; asm("add.rn.f16x2 %0, %1, %2;" : "=r"(r) : "r"(a), "r"(b)); return r;
}
__device__ __forceinline__ void mma_f16(float d[4], const unsigned a[4], unsigned b0, unsigned b1) {
    asm volatile("mma.sync.aligned.m16n8k16.row.col.f32.f16.f16.f32 "
        "{%0,%1,%2,%3}, {%4,%5,%6,%7}, {%8,%9}, {%0,%1,%2,%3};"
        : "+f"(d[0]), "+f"(d[1]), "+f"(d[2]), "+f"(d[3])
        : "r"(a[0]), "r"(a[1]), "r"(a[2]), "r"(a[3]), "r"(b0), "r"(b1));
}
__device__ __forceinline__ void ldsm4(unsigned& r0, unsigned& r1, unsigned& r2, unsigned& r3,
                                      uint32_t addr) {
    asm volatile("ldmatrix.sync.aligned.m8n8.x4.shared.b16 {%0,%1,%2,%3}, [%4];"
        : "=r"(r0), "=r"(r1), "=r"(r2), "=r"(r3) : "r"(addr));
}
__device__ __forceinline__ uint32_t smem_u32(const void* p) {
    uint32_t a;
    asm("{ .reg .u64 t; cvta.to.shared.u64 t, %1; cvt.u32.u64 %0, t; }" : "=r"(a) : "l"(p));
    return a;
}
__device__ __forceinline__ void cpa16(uint32_t dst, const void* src) {
    asm volatile("cp.async.cg.shared.global [%0], [%1], 16;" :: "r"(dst), "l"(src));
}
#define CPA_COMMIT() asm volatile("cp.async.commit_group;" ::: "memory")
#define CPA_WAIT1()  asm volatile("cp.async.wait_group 1;" ::: "memory")
#define CPA_WAIT0()  asm volatile("cp.async.wait_group 0;" ::: "memory")

// ---------------------------------------------------------------------------
// Kernel 0a: x fp32 -> fp16.
// ---------------------------------------------------------------------------
__global__ void __launch_bounds__(256) xconv_kernel(const float* __restrict__ x) {
    const size_t i8 = ((size_t)blockIdx.x * 256 + threadIdx.x) * 8;
    float4 a = *(const float4*)(x + i8);
    float4 b = *(const float4*)(x + i8 + 4);
    uint4 o;
    o.x = packh(a.x, a.y); o.y = packh(a.z, a.w);
    o.z = packh(b.x, b.y); o.w = packh(b.z, b.w);
    *(uint4*)(g_xh + i8) = o;
}

// ---------------------------------------------------------------------------
// Kernel 0b: Wq/Wk/Wv -> g_Wqkvt [h][m*64+e][d] fp16. Q pre-scaled.
// ---------------------------------------------------------------------------
__global__ void wqkvt_kernel(const float* __restrict__ Wq,
                             const float* __restrict__ Wk,
                             const float* __restrict__ Wv) {
    __shared__ float tile[32][33];
    const int e0 = blockIdx.x * 32, d0 = blockIdx.y * 32;
    const int hm = blockIdx.z, h = hm / 3, m = hm % 3;
    const int tx = threadIdx.x, ty = threadIdx.y;
    const float* W = ((m == 0) ? Wq : (m == 1) ? Wk : Wv) + (size_t)h * 4096;
    const float sc = (m == 0) ? 0.125f * 1.4426950408889634f : 1.0f;
    #pragma unroll
    for (int j = 0; j < 4; j++)
        tile[ty + j * 8][tx] = W[(size_t)(d0 + ty + j * 8) * 64 + e0 + tx];
    __syncthreads();
    #pragma unroll
    for (int j = 0; j < 4; j++)
        g_Wqkvt[((size_t)h * 192 + m * 64 + e0 + ty + j * 8) * HD_ + d0 + tx] =
            __float2half_rn(tile[tx][ty + j * 8] * sc);
}

// ---------------------------------------------------------------------------
// Kernel 1: fused QKV via fp16 MMA (unchanged).
// ---------------------------------------------------------------------------
#define QK_ROWB 144
#define QK_XS   (128 * QK_ROWB)
#define QK_WS   (192 * QK_ROWB)
#define QK_SMEM (QK_XS + QK_WS)

__global__ void __launch_bounds__(256, 2) qkv_mma_kernel() {
    extern __shared__ __align__(16) char dsm[];
    const uint32_t sxs = smem_u32(dsm);
    const uint32_t sws = sxs + QK_XS;

    const int st = blockIdx.x, h = blockIdx.y, b = blockIdx.z;
    const int s0 = st * 128;
    const int bh = b * NH_ + h;
    const int tid = threadIdx.x;
    const int wid = tid >> 5, lane = tid & 31;
    const int g = lane >> 2, tg = lane & 3;
    const int warp_m = wid & 1;
    const int warp_n = wid >> 1;

    const uint32_t plA = (uint32_t)(((lane & 7) + ((lane >> 3) & 1) * 8) * QK_ROWB
                                    + (lane >> 4) * 16);
    const uint32_t plB = (uint32_t)(((lane & 7) + ((lane >> 4) << 3)) * QK_ROWB
                                    + ((lane >> 3) & 1) * 16);

    {
        #pragma unroll
        for (int ii = 0; ii < 4; ii++) {
            int i = tid + ii * 256;
            int row = i >> 3, c8 = i & 7;
            cpa16(sxs + row * QK_ROWB + c8 * 16,
                  g_xh + ((size_t)(b * S_ + s0 + row)) * HID_ + h * HD_ + c8 * 8);
        }
        #pragma unroll
        for (int ii = 0; ii < 6; ii++) {
            int i = tid + ii * 256;
            int row = i >> 3, c8 = i & 7;
            cpa16(sws + row * QK_ROWB + c8 * 16,
                  g_Wqkvt + ((size_t)h * 192 + row) * HD_ + c8 * 8);
        }
        CPA_COMMIT();
        CPA_WAIT0();
        __syncthreads();
    }

    float acc[4][6][4];
    #pragma unroll
    for (int mt = 0; mt < 4; mt++)
        #pragma unroll
        for (int nt = 0; nt < 6; nt++)
            { acc[mt][nt][0] = acc[mt][nt][1] = acc[mt][nt][2] = acc[mt][nt][3] = 0.0f; }

    #pragma unroll
    for (int ks = 0; ks < 4; ks++) {
        unsigned ah[4][4];
        #pragma unroll
        for (int mt = 0; mt < 4; mt++)
            ldsm4(ah[mt][0], ah[mt][1], ah[mt][2], ah[mt][3],
                  sxs + (warp_m * 64 + mt * 16) * QK_ROWB + ks * 32 + plA);
        unsigned bf[6][2];
        #pragma unroll
        for (int ntp = 0; ntp < 3; ntp++)
            ldsm4(bf[2 * ntp][0], bf[2 * ntp][1], bf[2 * ntp + 1][0], bf[2 * ntp + 1][1],
                  sws + (warp_n * 48 + ntp * 16) * QK_ROWB + ks * 32 + plB);
        #pragma unroll
        for (int mt = 0; mt < 4; mt++)
            #pragma unroll
            for (int nt = 0; nt < 6; nt++)
                mma_f16(acc[mt][nt], ah[mt], bf[nt][0], bf[nt][1]);
    }

    __syncthreads();

    #pragma unroll
    for (int mt = 0; mt < 4; mt++) {
        const int r0 = warp_m * 64 + mt * 16 + g;
        #pragma unroll
        for (int nt = 0; nt < 6; nt++) {
            const int col = warp_n * 48 + nt * 8 + 2 * tg;
            const int m = col >> 6, e = col & 63;
            const unsigned p0 = packh(acc[mt][nt][0], acc[mt][nt][1]);
            const unsigned p1 = packh(acc[mt][nt][2], acc[mt][nt][3]);
            if (m == 0) {
                __half* q = g_Qh + ((size_t)bh * S_ + s0) * HD_;
                *(unsigned*)(q + (size_t)r0 * HD_ + e)       = p0;
                *(unsigned*)(q + (size_t)(r0 + 8) * HD_ + e) = p1;
            } else if (m == 1) {
                __half* k = g_Kh + ((size_t)bh * S_ + s0) * HD_;
                *(unsigned*)(k + (size_t)r0 * HD_ + e)       = p0;
                *(unsigned*)(k + (size_t)(r0 + 8) * HD_ + e) = p1;
            } else {
                *(unsigned*)(dsm + r0 * QK_ROWB + e * 2)       = p0;
                *(unsigned*)(dsm + (r0 + 8) * QK_ROWB + e * 2) = p1;
            }
        }
    }
    __syncthreads();

    {
        const int d = tid >> 2;
        const int sc0 = (tid & 3) * 32;
        const __half* vsrc = (const __half*)dsm;
        __half* vdst = g_Vt + ((size_t)bh * HD_ + d) * S_ + s0 + sc0;
        #pragma unroll
        for (int j = 0; j < 4; j++) {
            unsigned w0 = packh(__half2float(vsrc[(sc0 + j * 8 + 0) * 72 + d]),
                                __half2float(vsrc[(sc0 + j * 8 + 1) * 72 + d]));
            unsigned w1 = packh(__half2float(vsrc[(sc0 + j * 8 + 2) * 72 + d]),
                                __half2float(vsrc[(sc0 + j * 8 + 3) * 72 + d]));
            unsigned w2 = packh(__half2float(vsrc[(sc0 + j * 8 + 4) * 72 + d]),
                                __half2float(vsrc[(sc0 + j * 8 + 5) * 72 + d]));
            unsigned w3 = packh(__half2float(vsrc[(sc0 + j * 8 + 6) * 72 + d]),
                                __half2float(vsrc[(sc0 + j * 8 + 7) * 72 + d]));
            *(uint4*)(vdst + j * 8) = make_uint4(w0, w1, w2, w3);
        }
    }
}

// ---------------------------------------------------------------------------
// Kernel 1b: Wo -> transposed fp16 [n][k].
// ---------------------------------------------------------------------------
__global__ void wot_kernel(const float* __restrict__ Wo) {
    __shared__ float tile[32][33];
    const int n0 = blockIdx.x * 32, k0 = blockIdx.y * 32;
    const int tx = threadIdx.x, ty = threadIdx.y;
    #pragma unroll
    for (int j = 0; j < 4; j++)
        tile[ty + j * 8][tx] = Wo[(size_t)(k0 + ty + j * 8) * HID_ + n0 + tx];
    __syncthreads();
    #pragma unroll
    for (int j = 0; j < 4; j++)
        g_Wot[(size_t)(n0 + ty + j * 8) * HID_ + k0 + tx] = __float2half_rn(tile[tx][ty + j * 8]);
}

// ---------------------------------------------------------------------------
// Kernel 2: flash attention, fp16 MMA, static softmax (ex2.f16x2).
// NEW: 4 warps x 32 q-rows (2 m-tiles per warp) -> each K/V LDSM feeds
// 2 MMAs, halving smem crossbar traffic per FLOP (the measured co-limiter).
// 128-key tiles as two unsynced 64-key halves.
// ---------------------------------------------------------------------------
#define ATT_SUB   9216
#define ATT_STAGE 36864

__global__ void __launch_bounds__(128, 2) attn_kernel(const int* __restrict__ mask) {
    extern __shared__ __align__(16) char dsm[];
    const uint32_t sm0 = smem_u32(dsm);

    const int q0c = blockIdx.x * 128, h = blockIdx.y, b = blockIdx.z;
    const int bh  = b * NH_ + h;
    const int tid = threadIdx.x;
    const int w   = tid >> 5;            // 0..3, warp covers rows [w*32, w*32+32)
    const int lane = tid & 31;
    const int tg  = lane & 3;
    const int g   = lane >> 2;

    const uint32_t pl = (uint32_t)(((lane & 7) + ((lane >> 4) << 3)) * 144
                                   + ((lane >> 3) & 1) * 16);

    unsigned qh[2][4][4];
    #pragma unroll
    for (int mi = 0; mi < 2; mi++) {
        const __half* qb = g_Qh + ((size_t)bh * S_ + q0c + w * 32 + mi * 16) * HD_;
        #pragma unroll
        for (int ks = 0; ks < 4; ks++) {
            int c0 = ks * 16 + 2 * tg;
            qh[mi][ks][0] = *(const unsigned*)(qb + g * HD_ + c0);
            qh[mi][ks][1] = *(const unsigned*)(qb + (g + 8) * HD_ + c0);
            qh[mi][ks][2] = *(const unsigned*)(qb + g * HD_ + c0 + 8);
            qh[mi][ks][3] = *(const unsigned*)(qb + (g + 8) * HD_ + c0 + 8);
        }
    }

    float O[2][8][4];
    #pragma unroll
    for (int mi = 0; mi < 2; mi++)
        #pragma unroll
        for (int i = 0; i < 8; i++)
            { O[mi][i][0] = O[mi][i][1] = O[mi][i][2] = O[mi][i][3] = 0.0f; }
    float l0[2] = {0.0f, 0.0f}, l8[2] = {0.0f, 0.0f};

    const int* mrow0[2];
    const int* mrow8[2];
    #pragma unroll
    for (int mi = 0; mi < 2; mi++) {
        mrow0[mi] = mask + (size_t)(b * S_ + q0c + w * 32 + mi * 16 + g)     * S_;
        mrow8[mi] = mask + (size_t)(b * S_ + q0c + w * 32 + mi * 16 + g + 8) * S_;
    }

    auto issue_tile = [&](int t0, uint32_t sb) {
        #pragma unroll
        for (int ii = 0; ii < 8; ii++) {      // K: 128 rows x 8 chunks
            int i = tid + ii * 128;
            int krow = i >> 3, c8 = i & 7;
            uint32_t dst = sb + (krow >> 6) * ATT_SUB + (krow & 63) * 144 + c8 * 16;
            cpa16(dst, g_Kh + ((size_t)bh * S_ + t0 + krow) * HD_ + c8 * 8);
        }
        #pragma unroll
        for (int ii = 0; ii < 8; ii++) {      // V: 64 d-rows x 16 chunks
            int i = tid + ii * 128;
            int d = i >> 4, c16 = i & 15;
            int sub = c16 >> 3, c8 = c16 & 7;
            uint32_t dst = sb + 2 * ATT_SUB + sub * ATT_SUB + d * 144 + c8 * 16;
            cpa16(dst, g_Vt + ((size_t)bh * HD_ + d) * S_ + t0 + sub * 64 + c8 * 8);
        }
        CPA_COMMIT();
    };

    issue_tile(0, sm0);

    #pragma unroll 1
    for (int ti = 0; ti < S_ / 128; ti++) {
        const int t0 = ti * 128;
        const uint32_t sbu = sm0 + (ti & 1) * ATT_STAGE;
        if (ti + 1 < S_ / 128) {
            issue_tile(t0 + 128, sm0 + ((ti + 1) & 1) * ATT_STAGE);
            CPA_WAIT1();
        } else {
            CPA_WAIT0();
        }
        __syncthreads();

        #pragma unroll 1
        for (int sub = 0; sub < 2; sub++) {   // no barrier between halves
            const uint32_t sbk = sbu + sub * ATT_SUB;
            const uint32_t sbv = sbu + 2 * ATT_SUB + sub * ATT_SUB;
            const int tk0 = t0 + sub * 64;

            unsigned mw0[2][8], mw8v[2][8];
            #pragma unroll
            for (int mi = 0; mi < 2; mi++)
                #pragma unroll
                for (int nt = 0; nt < 8; nt++) {
                    int2 mk  = *(const int2*)(mrow0[mi] + tk0 + nt * 8 + 2 * tg);
                    int2 mk8 = *(const int2*)(mrow8[mi] + tk0 + nt * 8 + 2 * tg);
                    mw0[mi][nt]  = (mk.x  ? 0u : 0x0000FFFFu) | (mk.y  ? 0u : 0xFFFF0000u);
                    mw8v[mi][nt] = (mk8.x ? 0u : 0x0000FFFFu) | (mk8.y ? 0u : 0xFFFF0000u);
                }

            // --- S = Q K^T: each K fragment feeds both m-tiles ---
            float S[2][8][4];
            #pragma unroll
            for (int mi = 0; mi < 2; mi++)
                #pragma unroll
                for (int i = 0; i < 8; i++)
                    { S[mi][i][0] = S[mi][i][1] = S[mi][i][2] = S[mi][i][3] = 0.0f; }
            #pragma unroll
            for (int ks = 0; ks < 4; ks++) {
                #pragma unroll
                for (int ntp = 0; ntp < 4; ntp++) {
                    unsigned h0, h1, h2, h3;
                    ldsm4(h0, h1, h2, h3, sbk + ntp * 2304u + ks * 32u + pl);
                    #pragma unroll
                    for (int mi = 0; mi < 2; mi++) {
                        mma_f16(S[mi][2 * ntp],     qh[mi][ks], h0, h1);
                        mma_f16(S[mi][2 * ntp + 1], qh[mi][ks], h2, h3);
                    }
                }
            }

            // --- softmax: p2 = ex2.f16x2; numerator = p2 & maskword ---
            unsigned P0[2][8], P8[2][8];
            #pragma unroll
            for (int mi = 0; mi < 2; mi++) {
                unsigned lh = 0u, lh8 = 0u;
                #pragma unroll
                for (int nt = 0; nt < 8; nt++) {
                    unsigned p2  = ex2h2(packh(S[mi][nt][0], S[mi][nt][1]));
                    unsigned p28 = ex2h2(packh(S[mi][nt][2], S[mi][nt][3]));
                    lh  = hadd2u(lh,  p2);
                    lh8 = hadd2u(lh8, p28);
                    P0[mi][nt] = p2  & mw0[mi][nt];
                    P8[mi][nt] = p28 & mw8v[mi][nt];
                }
                float2 f  = __half22float2(*(__half2*)&lh);
                float2 f8 = __half22float2(*(__half2*)&lh8);
                l0[mi] += f.x + f.y;
                l8[mi] += f8.x + f8.y;
            }

            // --- O += P V: each V fragment feeds both m-tiles ---
            #pragma unroll
            for (int ksv = 0; ksv < 4; ksv++) {
                #pragma unroll
                for (int ntdp = 0; ntdp < 4; ntdp++) {
                    unsigned vh0, vh1, vh2, vh3;
                    ldsm4(vh0, vh1, vh2, vh3, sbv + ntdp * 2304u + ksv * 32u + pl);
                    #pragma unroll
                    for (int mi = 0; mi < 2; mi++) {
                        unsigned phi[4] = { P0[mi][2 * ksv], P8[mi][2 * ksv],
                                            P0[mi][2 * ksv + 1], P8[mi][2 * ksv + 1] };
                        mma_f16(O[mi][2 * ntdp],     phi, vh0, vh1);
                        mma_f16(O[mi][2 * ntdp + 1], phi, vh2, vh3);
                    }
                }
            }
        }
        __syncthreads();
    }

    #pragma unroll
    for (int mi = 0; mi < 2; mi++) {
        float a = l0[mi], c = l8[mi];
        a += __shfl_xor_sync(0xffffffffu, a, 1);
        a += __shfl_xor_sync(0xffffffffu, a, 2);
        c += __shfl_xor_sync(0xffffffffu, c, 1);
        c += __shfl_xor_sync(0xffffffffu, c, 2);
        const float inv0 = 1.0f / a;
        const float inv8 = 1.0f / c;
        const int q0 = q0c + w * 32 + mi * 16 + g;
        __half* c_g  = g_ctx + (size_t)(b * S_ + q0)     * HID_ + h * HD_;
        __half* c_g8 = g_ctx + (size_t)(b * S_ + q0 + 8) * HID_ + h * HD_;
        #pragma unroll
        for (int nt = 0; nt < 8; nt++) {
            const int cc = nt * 8 + 2 * tg;
            *(unsigned*)(c_g  + cc) = packh(O[mi][nt][0] * inv0, O[mi][nt][1] * inv0);
            *(unsigned*)(c_g8 + cc) = packh(O[mi][nt][2] * inv8, O[mi][nt][3] * inv8);
        }
    }
}

// ---------------------------------------------------------------------------
// Kernel 3: out = ctx @ Wo via fp16 MMA. K-chunk 64, LDSM, 2-stage cp.async.
// ---------------------------------------------------------------------------
#define OPS_ROWB  144
#define OPS_ARR   (128 * OPS_ROWB)
#define OPS_STAGE (2 * OPS_ARR)

__global__ void __launch_bounds__(256, 2) oproj_kernel(float* __restrict__ out) {
    extern __shared__ __align__(16) char dsm[];
    const uint32_t sm0 = smem_u32(dsm);

    const int tid = threadIdx.x;
    const int wid = tid >> 5, lane = tid & 31;
    const int g = lane >> 2, tg = lane & 3;
    const int warp_m = wid & 1;
    const int warp_n = wid >> 1;
    const int bn = blockIdx.x * 128;
    const int bm = blockIdx.y * 128;

    const uint32_t plA = (uint32_t)(((lane & 7) + ((lane >> 3) & 1) * 8) * OPS_ROWB
                                    + (lane >> 4) * 16);
    const uint32_t plB = (uint32_t)(((lane & 7) + ((lane >> 4) << 3)) * OPS_ROWB
                                    + ((lane >> 3) & 1) * 16);

    float acc[4][4][4];
    #pragma unroll
    for (int mt = 0; mt < 4; mt++)
        #pragma unroll
        for (int nt = 0; nt < 4; nt++)
            { acc[mt][nt][0] = acc[mt][nt][1] = acc[mt][nt][2] = acc[mt][nt][3] = 0.0f; }

    auto load_chunk = [&](int c) {
        const uint32_t sb = sm0 + (c & 1) * OPS_STAGE;
        const int k0 = c * 64;
        #pragma unroll
        for (int ii = 0; ii < 4; ii++) {
            int i = tid + ii * 256;
            int row = i >> 3, c8 = i & 7;
            uint32_t d = sb + row * OPS_ROWB + c8 * 16;
            cpa16(d,           g_ctx + (size_t)(bm + row) * HID_ + k0 + c8 * 8);
            cpa16(d + OPS_ARR, g_Wot + (size_t)(bn + row) * HID_ + k0 + c8 * 8);
        }
        CPA_COMMIT();
    };

    load_chunk(0);

    #pragma unroll 1
    for (int c = 0; c < HID_ / 64; c++) {
        const uint32_t sb = sm0 + (c & 1) * OPS_STAGE;
        if (c + 1 < HID_ / 64) {
            load_chunk(c + 1);
            CPA_WAIT1();
        } else {
            CPA_WAIT0();
        }
        __syncthreads();

        #pragma unroll
        for (int ks = 0; ks < 4; ks++) {
            unsigned ah[4][4];
            #pragma unroll
            for (int mt = 0; mt < 4; mt++)
                ldsm4(ah[mt][0], ah[mt][1], ah[mt][2], ah[mt][3],
                      sb + (warp_m * 64 + mt * 16) * OPS_ROWB + ks * 32 + plA);
            unsigned bh[4][2];
            #pragma unroll
            for (int ntp = 0; ntp < 2; ntp++)
                ldsm4(bh[2 * ntp][0], bh[2 * ntp][1], bh[2 * ntp + 1][0], bh[2 * ntp + 1][1],
                      sb + OPS_ARR + (warp_n * 32 + ntp * 16) * OPS_ROWB + ks * 32 + plB);
            #pragma unroll
            for (int mt = 0; mt < 4; mt++)
                #pragma unroll
                for (int nt = 0; nt < 4; nt++)
                    mma_f16(acc[mt][nt], ah[mt], bh[nt][0], bh[nt][1]);
        }
        __syncthreads();
    }

    #pragma unroll
    for (int mt = 0; mt < 4; mt++) {
        const int row = bm + warp_m * 64 + mt * 16 + g;
        #pragma unroll
        for (int nt = 0; nt < 4; nt++) {
            const int col = bn + warp_n * 32 + nt * 8 + 2 * tg;
            *(float2*)(out + (size_t)row * HID_ + col)       = make_float2(acc[mt][nt][0], acc[mt][nt][1]);
            *(float2*)(out + (size_t)(row + 8) * HID_ + col) = make_float2(acc[mt][nt][2], acc[mt][nt][3]);
        }
    }
}

// ---------------------------------------------------------------------------
extern "C" void kernel_launch(void* const* d_in, const int* in_sizes, int n_in,
                              void* d_out, int out_size) {
    const float* x    = (const float*)d_in[0];
    const int*   mask = (const int*)d_in[1];   // jax bool promoted to int32
    const float* Wq   = (const float*)d_in[2];
    const float* Wk   = (const float*)d_in[3];
    const float* Wv   = (const float*)d_in[4];
    const float* Wo   = (const float*)d_in[5];
    float*       out  = (float*)d_out;

    cudaFuncSetAttribute(qkv_mma_kernel, cudaFuncAttributeMaxDynamicSharedMemorySize, QK_SMEM);
    cudaFuncSetAttribute(attn_kernel,    cudaFuncAttributeMaxDynamicSharedMemorySize, 2 * ATT_STAGE);
    cudaFuncSetAttribute(oproj_kernel,   cudaFuncAttributeMaxDynamicSharedMemorySize, 2 * OPS_STAGE);

    xconv_kernel<<<(B_ * S_ * HID_) / (256 * 8), 256>>>(x);
    wqkvt_kernel<<<dim3(2, 2, NH_ * 3), dim3(32, 8)>>>(Wq, Wk, Wv);
    wot_kernel<<<dim3(HID_ / 32, HID_ / 32), dim3(32, 8)>>>(Wo);
    qkv_mma_kernel<<<dim3(S_ / 128, NH_, B_), 256, QK_SMEM>>>();
    attn_kernel<<<dim3(S_ / 128, NH_, B_), 128, 2 * ATT_STAGE>>>(mask);
    oproj_kernel<<<dim3(HID_ / 128, (B_ * S_) / 128), 256, 2 * OPS_STAGE>>>(out);
}